// round 13
// baseline (speedup 1.0000x reference)
#include <cuda_runtime.h>
#include <cuda_bf16.h>
#include <cstdint>

#define NS 512
#define NR 384
#define CM 256
#define CO 32
#define CZ 128
#define MTOT (NR*CO)        // 12288
#define NPAIR (NR*NR)       // 147456
#define KOUT 1024           // 32*32

// bf16 tiles: 32 bf16 (64B) + 16B pad
#define ROWB 80
#define TILE_BYTES (128 * ROWB)      // 10240
#define STAGE_BYTES (4 * TILE_BYTES) // 40960 (epi gemm)
#define PIPE_BYTES (2 * STAGE_BYTES) // 81920

// fp8 tiles: 32 fp8 (32B) + 16B pad
#define R8B 48
#define TILE8 (128 * R8B)            // 6144
#define OSTAGE (2 * TILE_BYTES + 4 * TILE8)  // 45056 (outer gemm)
#define OPIPE (2 * OSTAGE)                   // 90112

// ---------------- static device scratch ----------------
__device__ float g_leftf [NS * MTOT];            // [a][m] fp32 staging
__device__ float g_rightf[NS * MTOT];
__device__ float g_rnorm [NPAIR];
__device__ unsigned short g_lhi[MTOT * NS];      // [m][a] bf16 hi, K-major
__device__ unsigned short g_rhi[MTOT * NS];
__device__ unsigned char  g_lh8[MTOT * NS];      // e4m3(hi * 2^-4)
__device__ unsigned char  g_ll8[MTOT * NS];      // e4m3(lo * 2^+4)
__device__ unsigned char  g_rh8[MTOT * NS];
__device__ unsigned char  g_rl8[MTOT * NS];
__device__ unsigned short g_ohi[(size_t)NPAIR * KOUT];  // outer [p][c*32+e] hi
__device__ unsigned short g_olo[(size_t)NPAIR * KOUT];  // outer lo
__device__ unsigned short g_whi[CZ * KOUT];      // w^T [f][ce] hi
__device__ unsigned short g_wlo[CZ * KOUT];

// ---------------- helpers ----------------
__device__ __forceinline__ uint32_t smem_u32(const void* p) {
    uint32_t a;
    asm("{ .reg .u64 t; cvta.to.shared.u64 t, %1; cvt.u32.u64 %0, t; }" : "=r"(a) : "l"(p));
    return a;
}
__device__ __forceinline__ void split_bf16(float x, unsigned short& h, unsigned short& l) {
    __nv_bfloat16 bh = __float2bfloat16(x);
    float r = x - __bfloat162float(bh);
    __nv_bfloat16 bl = __float2bfloat16(r);
    h = __bfloat16_as_ushort(bh);
    l = __bfloat16_as_ushort(bl);
}
__device__ __forceinline__ void split2(float x0, float x1, uint32_t& h, uint32_t& l) {
    unsigned short h0, l0, h1, l1;
    split_bf16(x0, h0, l0);
    split_bf16(x1, h1, l1);
    h = (uint32_t)h0 | ((uint32_t)h1 << 16);
    l = (uint32_t)l0 | ((uint32_t)l1 << 16);
}
// packs: hi-byte = e4m3(a), lo-byte = e4m3(b)
__device__ __forceinline__ unsigned short cvt_e4m3x2(float a, float b) {
    unsigned short u;
    asm("cvt.rn.satfinite.e4m3x2.f32 %0, %1, %2;" : "=h"(u) : "f"(a), "f"(b));
    return u;
}
__device__ __forceinline__ void ldsm_x4(uint32_t addr, uint32_t r[4]) {
    asm volatile("ldmatrix.sync.aligned.m8n8.x4.shared.b16 {%0,%1,%2,%3}, [%4];"
                 : "=r"(r[0]), "=r"(r[1]), "=r"(r[2]), "=r"(r[3]) : "r"(addr));
}
__device__ __forceinline__ void mma_bf16(float c[4], const uint32_t a[4],
                                         uint32_t b0, uint32_t b1) {
    asm volatile(
        "mma.sync.aligned.m16n8k16.row.col.f32.bf16.bf16.f32 "
        "{%0,%1,%2,%3}, {%4,%5,%6,%7}, {%8,%9}, {%0,%1,%2,%3};"
        : "+f"(c[0]), "+f"(c[1]), "+f"(c[2]), "+f"(c[3])
        : "r"(a[0]), "r"(a[1]), "r"(a[2]), "r"(a[3]), "r"(b0), "r"(b1));
}
__device__ __forceinline__ void mma_e4m3(float c[4], const uint32_t a[4],
                                         uint32_t b0, uint32_t b1) {
    asm volatile(
        "mma.sync.aligned.m16n8k32.row.col.f32.e4m3.e4m3.f32 "
        "{%0,%1,%2,%3}, {%4,%5,%6,%7}, {%8,%9}, {%0,%1,%2,%3};"
        : "+f"(c[0]), "+f"(c[1]), "+f"(c[2]), "+f"(c[3])
        : "r"(a[0]), "r"(a[1]), "r"(a[2]), "r"(a[3]), "r"(b0), "r"(b1));
}

// async-copy one [128 rows x 32 bf16] K-chunk tile into padded smem
__device__ __forceinline__ void load_tile_async(const unsigned short* __restrict__ g,
                                                size_t ldk, int k0,
                                                uint32_t sdst, int t) {
    #pragma unroll
    for (int i = 0; i < 2; i++) {
        int vid = i * 256 + t;      // 0..511
        int row = vid >> 2;         // 0..127
        int c8  = (vid & 3) << 3;   // 0,8,16,24 (bf16 elems)
        const void* src = g + (size_t)row * ldk + k0 + c8;
        uint32_t dst = sdst + row * ROWB + c8 * 2;
        asm volatile("cp.async.cg.shared.global [%0], [%1], 16;"
                     :: "r"(dst), "l"(src) : "memory");
    }
}
// async-copy one [128 rows x 32 fp8] tile (32B rows, pitch 48)
__device__ __forceinline__ void load_tile8_async(const unsigned char* __restrict__ g,
                                                 size_t ldk, int k0b,
                                                 uint32_t sdst, int t) {
    int row = t >> 1, half = t & 1;
    const void* src = g + (size_t)row * ldk + k0b + half * 16;
    uint32_t dst = sdst + row * R8B + half * 16;
    asm volatile("cp.async.cg.shared.global [%0], [%1], 16;"
                 :: "r"(dst), "l"(src) : "memory");
}

// ---------------------------------------------------------------------------
// epi-gemm mainloop (bf16 split 3-pass, unchanged)
// ---------------------------------------------------------------------------
__device__ __forceinline__ void gemm_main(
    const unsigned short* __restrict__ Ah, const unsigned short* __restrict__ Al, size_t lda,
    const unsigned short* __restrict__ Bh, const unsigned short* __restrict__ Bl, size_t ldb,
    int nchunks, uint32_t sb, float acc[2][8][4])
{
    int t = threadIdx.x, lane = t & 31, warp = t >> 5;
    int mb = (warp >> 1) * 32, nb = (warp & 1) * 64;
    int g8 = lane >> 3;
    int a_row = (lane & 7) + ((g8 & 1) << 3);
    int a_k   = (g8 >> 1) << 3;
    int b_row = (lane & 7) + ((g8 >> 1) << 3);
    int b_k   = (g8 & 1) << 3;

    #pragma unroll
    for (int s = 0; s < 2; s++) {
        uint32_t bb = sb + s * STAGE_BYTES;
        int k0 = s * 32;
        load_tile_async(Ah, lda, k0, bb,                  t);
        load_tile_async(Al, lda, k0, bb + TILE_BYTES,     t);
        load_tile_async(Bh, ldb, k0, bb + 2 * TILE_BYTES, t);
        load_tile_async(Bl, ldb, k0, bb + 3 * TILE_BYTES, t);
        asm volatile("cp.async.commit_group;" ::: "memory");
    }

    for (int kc = 0; kc < nchunks; kc++) {
        if (kc + 1 < nchunks)
            asm volatile("cp.async.wait_group 1;" ::: "memory");
        else
            asm volatile("cp.async.wait_group 0;" ::: "memory");
        __syncthreads();

        uint32_t bb  = sb + (kc & 1) * STAGE_BYTES;
        uint32_t uAh = bb, uAl = bb + TILE_BYTES;
        uint32_t uBh = bb + 2 * TILE_BYTES, uBl = bb + 3 * TILE_BYTES;

        #pragma unroll
        for (int ks = 0; ks < 32; ks += 16) {
            uint32_t fAh[2][4], fAl[2][4];
            #pragma unroll
            for (int i = 0; i < 2; i++) {
                uint32_t ro = (uint32_t)((mb + i * 16 + a_row) * ROWB + (ks + a_k) * 2);
                ldsm_x4(uAh + ro, fAh[i]);
                ldsm_x4(uAl + ro, fAl[i]);
            }
            #pragma unroll
            for (int jj = 0; jj < 4; jj++) {
                uint32_t fBh[4], fBl[4];
                uint32_t ro = (uint32_t)((nb + jj * 16 + b_row) * ROWB + (ks + b_k) * 2);
                ldsm_x4(uBh + ro, fBh);
                ldsm_x4(uBl + ro, fBl);
                mma_bf16(acc[0][2 * jj],     fAh[0], fBh[0], fBh[1]);
                mma_bf16(acc[1][2 * jj],     fAh[1], fBh[0], fBh[1]);
                mma_bf16(acc[0][2 * jj + 1], fAh[0], fBh[2], fBh[3]);
                mma_bf16(acc[1][2 * jj + 1], fAh[1], fBh[2], fBh[3]);
                mma_bf16(acc[0][2 * jj],     fAh[0], fBl[0], fBl[1]);
                mma_bf16(acc[1][2 * jj],     fAh[1], fBl[0], fBl[1]);
                mma_bf16(acc[0][2 * jj + 1], fAh[0], fBl[2], fBl[3]);
                mma_bf16(acc[1][2 * jj + 1], fAh[1], fBl[2], fBl[3]);
                mma_bf16(acc[0][2 * jj],     fAl[0], fBh[0], fBh[1]);
                mma_bf16(acc[1][2 * jj],     fAl[1], fBh[0], fBh[1]);
                mma_bf16(acc[0][2 * jj + 1], fAl[0], fBh[2], fBh[3]);
                mma_bf16(acc[1][2 * jj + 1], fAl[1], fBh[2], fBh[3]);
            }
        }
        __syncthreads();

        if (kc + 2 < nchunks) {
            uint32_t nbuf = sb + (kc & 1) * STAGE_BYTES;
            int k0 = (kc + 2) * 32;
            load_tile_async(Ah, lda, k0, nbuf,                  t);
            load_tile_async(Al, lda, k0, nbuf + TILE_BYTES,     t);
            load_tile_async(Bh, ldb, k0, nbuf + 2 * TILE_BYTES, t);
            load_tile_async(Bl, ldb, k0, nbuf + 3 * TILE_BYTES, t);
            asm volatile("cp.async.commit_group;" ::: "memory");
        }
    }
}

// ---------------------------------------------------------------------------
// Kernel 1: LayerNorm + projections (fp32 staging, [a][m])
// ---------------------------------------------------------------------------
__global__ __launch_bounds__(256) void ln_proj_kernel(
    const float* __restrict__ act, const float* __restrict__ mask,
    const float* __restrict__ ln_w, const float* __restrict__ ln_b,
    const float* __restrict__ lw, const float* __restrict__ lb,
    const float* __restrict__ rw, const float* __restrict__ rb)
{
    int idx = blockIdx.x;
    int a = idx / NR, b = idx - a * NR;
    int t = threadIdx.x;
    __shared__ float s_act[CM];
    __shared__ float red1[8], red2[8];

    float x = act[(size_t)idx * CM + t];
    float s1 = x, s2 = x * x;
    #pragma unroll
    for (int o = 16; o; o >>= 1) {
        s1 += __shfl_xor_sync(0xffffffffu, s1, o);
        s2 += __shfl_xor_sync(0xffffffffu, s2, o);
    }
    int warp = t >> 5, lane = t & 31;
    if (lane == 0) { red1[warp] = s1; red2[warp] = s2; }
    __syncthreads();
    if (t < 32) {
        float a1 = (t < 8) ? red1[t] : 0.f;
        float a2 = (t < 8) ? red2[t] : 0.f;
        #pragma unroll
        for (int o = 4; o; o >>= 1) {
            a1 += __shfl_xor_sync(0xffffffffu, a1, o);
            a2 += __shfl_xor_sync(0xffffffffu, a2, o);
        }
        if (t == 0) { red1[0] = a1; red2[0] = a2; }
    }
    __syncthreads();
    float mu  = red1[0] * (1.f / CM);
    float var = red2[0] * (1.f / CM) - mu * mu;
    float inv = rsqrtf(var + 1e-5f);
    s_act[t] = (x - mu) * inv * ln_w[t] + ln_b[t];
    __syncthreads();

    int o = t >> 2, q = t & 3;
    const float* w = (o < CO) ? (lw + o * CM) : (rw + (o - CO) * CM);
    const float4* sa4 = (const float4*)(s_act + q * 64);
    const float4* w4  = (const float4*)(w + q * 64);
    float acc = 0.f;
    #pragma unroll
    for (int i = 0; i < 16; i++) {
        float4 xa = sa4[i], xw = w4[i];
        acc += xa.x * xw.x + xa.y * xw.y + xa.z * xw.z + xa.w * xw.w;
    }
    acc += __shfl_xor_sync(0xffffffffu, acc, 1);
    acc += __shfl_xor_sync(0xffffffffu, acc, 2);
    if (q == 0) {
        float mv = mask[a * NR + b];
        if (o < CO) g_leftf [(size_t)a * MTOT + b * CO + o]        = mv * (acc + lb[o]);
        else        g_rightf[(size_t)a * MTOT + b * CO + (o - CO)] = mv * (acc + rb[o - CO]);
    }
}

// ---------------------------------------------------------------------------
// Kernel 2: transpose [a][m] fp32 -> [m][a]: bf16 hi + e4m3 hi/lo (scaled)
// ---------------------------------------------------------------------------
__global__ __launch_bounds__(256) void transpose_split_kernel()
{
    __shared__ float tile[32][33];
    int m0 = blockIdx.x * 32, a0 = blockIdx.y * 32;
    const float* src = blockIdx.z ? g_rightf : g_leftf;
    unsigned short* dhi = blockIdx.z ? g_rhi : g_lhi;
    unsigned char*  d8h = blockIdx.z ? g_rh8 : g_lh8;
    unsigned char*  d8l = blockIdx.z ? g_rl8 : g_ll8;
    int tx = threadIdx.x, ty = threadIdx.y;
    #pragma unroll
    for (int r = 0; r < 4; r++)
        tile[ty + 8 * r][tx] = src[(size_t)(a0 + ty + 8 * r) * MTOT + m0 + tx];
    __syncthreads();
    #pragma unroll
    for (int r = 0; r < 4; r++) {
        int m = m0 + ty + 8 * r;
        float x = tile[tx][ty + 8 * r];
        __nv_bfloat16 bh = __float2bfloat16(x);
        float hf = __bfloat162float(bh);
        float lf = x - hf;
        dhi[(size_t)m * NS + a0 + tx] = __bfloat16_as_ushort(bh);
        float h4 = hf * 0.0625f;   // 2^-4
        float l4 = lf * 16.0f;     // 2^+4
        float h4p = __shfl_xor_sync(0xffffffffu, h4, 1);
        float l4p = __shfl_xor_sync(0xffffffffu, l4, 1);
        if (!(tx & 1)) {
            size_t off = (size_t)m * NS + a0 + tx;
            *(unsigned short*)(d8h + off) = cvt_e4m3x2(h4p, h4);
            *(unsigned short*)(d8l + off) = cvt_e4m3x2(l4p, l4);
        }
    }
}

// ---------------------------------------------------------------------------
// Kernel 3: reciprocal mask norm
// ---------------------------------------------------------------------------
__global__ void norm_kernel(const float* __restrict__ mask)
{
    int b = blockIdx.x * 16 + threadIdx.x;
    int d = blockIdx.y * 16 + threadIdx.y;
    float acc = 0.f;
    #pragma unroll 8
    for (int a = 0; a < NS; a++)
        acc += mask[a * NR + b] * mask[a * NR + d];
    g_rnorm[b * NR + d] = 1.f / (1e-3f + acc);
}

// ---------------------------------------------------------------------------
// Kernel 4: w^T split prep  wT[f][c*32+e] = w[c,e,f]
// ---------------------------------------------------------------------------
__global__ void wprep_kernel(const float* __restrict__ w)
{
    int ce = blockIdx.x, f = threadIdx.x;
    unsigned short h, l;
    split_bf16(w[(size_t)ce * CZ + f], h, l);
    g_whi[(size_t)f * KOUT + ce] = h;
    g_wlo[(size_t)f * KOUT + ce] = l;
}

// ---------------------------------------------------------------------------
// Kernel 5: outer-product GEMM (12288x12288x512) -> g_ohi/g_olo
//           hh pass in bf16-k16, cross passes in e4m3-k32 (2x denser)
// ---------------------------------------------------------------------------
__global__ __launch_bounds__(256, 2) void gemm_outer_kernel()
{
    extern __shared__ __align__(16) unsigned char dsm[];
    uint32_t sb = smem_u32(dsm);

    int bi = blockIdx.x, bj = blockIdx.y;
    int t = threadIdx.x, lane = t & 31, warp = t >> 5;
    int wm = warp >> 1, wn = warp & 1;
    int mb = wm * 32, nb = wn * 64;
    int g8 = lane >> 3;
    int a_row = (lane & 7) + ((g8 & 1) << 3);
    int a_k   = (g8 >> 1) << 3;       // bf16 elems
    int b_row = (lane & 7) + ((g8 >> 1) << 3);
    int b_k   = (g8 & 1) << 3;
    int a_kb8 = (g8 >> 1) << 4;       // fp8 byte offset
    int b_kb8 = (g8 & 1) << 4;

    const unsigned short* Ah = g_lhi + (size_t)bi * 128 * NS;
    const unsigned short* Bh = g_rhi + (size_t)bj * 128 * NS;
    const unsigned char*  A8h = g_lh8 + (size_t)bi * 128 * NS;
    const unsigned char*  A8l = g_ll8 + (size_t)bi * 128 * NS;
    const unsigned char*  B8h = g_rh8 + (size_t)bj * 128 * NS;
    const unsigned char*  B8l = g_rl8 + (size_t)bj * 128 * NS;

    float acc[2][8][4];
    #pragma unroll
    for (int i = 0; i < 2; i++)
        #pragma unroll
        for (int j = 0; j < 8; j++)
            #pragma unroll
            for (int q = 0; q < 4; q++) acc[i][j][q] = 0.f;

    const int NCH = NS / 32;   // 16

    #pragma unroll
    for (int s = 0; s < 2; s++) {
        uint32_t bb = sb + s * OSTAGE;
        int k0 = s * 32;
        load_tile_async (Ah,  NS, k0, bb,                            t);
        load_tile_async (Bh,  NS, k0, bb + TILE_BYTES,               t);
        load_tile8_async(A8h, NS, k0, bb + 2 * TILE_BYTES,           t);
        load_tile8_async(A8l, NS, k0, bb + 2 * TILE_BYTES + TILE8,   t);
        load_tile8_async(B8h, NS, k0, bb + 2 * TILE_BYTES + 2*TILE8, t);
        load_tile8_async(B8l, NS, k0, bb + 2 * TILE_BYTES + 3*TILE8, t);
        asm volatile("cp.async.commit_group;" ::: "memory");
    }

    for (int kc = 0; kc < NCH; kc++) {
        if (kc + 1 < NCH)
            asm volatile("cp.async.wait_group 1;" ::: "memory");
        else
            asm volatile("cp.async.wait_group 0;" ::: "memory");
        __syncthreads();

        uint32_t bb   = sb + (kc & 1) * OSTAGE;
        uint32_t uAh  = bb, uBh = bb + TILE_BYTES;
        uint32_t u8Ah = bb + 2 * TILE_BYTES;
        uint32_t u8Al = u8Ah + TILE8;
        uint32_t u8Bh = u8Ah + 2 * TILE8;
        uint32_t u8Bl = u8Ah + 3 * TILE8;

        // ---- hh pass (bf16, K=32 in 2 k16 steps) ----
        #pragma unroll
        for (int ks = 0; ks < 32; ks += 16) {
            uint32_t fAh[2][4];
            #pragma unroll
            for (int i = 0; i < 2; i++)
                ldsm_x4(uAh + (uint32_t)((mb + i * 16 + a_row) * ROWB + (ks + a_k) * 2),
                        fAh[i]);
            #pragma unroll
            for (int jj = 0; jj < 4; jj++) {
                uint32_t fBh[4];
                ldsm_x4(uBh + (uint32_t)((nb + jj * 16 + b_row) * ROWB + (ks + b_k) * 2),
                        fBh);
                mma_bf16(acc[0][2 * jj],     fAh[0], fBh[0], fBh[1]);
                mma_bf16(acc[1][2 * jj],     fAh[1], fBh[0], fBh[1]);
                mma_bf16(acc[0][2 * jj + 1], fAh[0], fBh[2], fBh[3]);
                mma_bf16(acc[1][2 * jj + 1], fAh[1], fBh[2], fBh[3]);
            }
        }

        // ---- cross passes (e4m3 k32: hi*lo + lo*hi, scale 2^-4 * 2^4 = 1) ----
        {
            uint32_t fA8h[2][4], fA8l[2][4];
            #pragma unroll
            for (int i = 0; i < 2; i++) {
                uint32_t ro = (uint32_t)((mb + i * 16 + a_row) * R8B + a_kb8);
                ldsm_x4(u8Ah + ro, fA8h[i]);
                ldsm_x4(u8Al + ro, fA8l[i]);
            }
            #pragma unroll
            for (int jj = 0; jj < 4; jj++) {
                uint32_t fB8l[4], fB8h[4];
                uint32_t ro = (uint32_t)((nb + jj * 16 + b_row) * R8B + b_kb8);
                ldsm_x4(u8Bl + ro, fB8l);
                ldsm_x4(u8Bh + ro, fB8h);
                mma_e4m3(acc[0][2 * jj],     fA8h[0], fB8l[0], fB8l[1]);
                mma_e4m3(acc[1][2 * jj],     fA8h[1], fB8l[0], fB8l[1]);
                mma_e4m3(acc[0][2 * jj + 1], fA8h[0], fB8l[2], fB8l[3]);
                mma_e4m3(acc[1][2 * jj + 1], fA8h[1], fB8l[2], fB8l[3]);
                mma_e4m3(acc[0][2 * jj],     fA8l[0], fB8h[0], fB8h[1]);
                mma_e4m3(acc[1][2 * jj],     fA8l[1], fB8h[0], fB8h[1]);
                mma_e4m3(acc[0][2 * jj + 1], fA8l[0], fB8h[2], fB8h[3]);
                mma_e4m3(acc[1][2 * jj + 1], fA8l[1], fB8h[2], fB8h[3]);
            }
        }
        __syncthreads();

        if (kc + 2 < NCH) {
            uint32_t nbuf = sb + (kc & 1) * OSTAGE;
            int k0 = (kc + 2) * 32;
            load_tile_async (Ah,  NS, k0, nbuf,                            t);
            load_tile_async (Bh,  NS, k0, nbuf + TILE_BYTES,               t);
            load_tile8_async(A8h, NS, k0, nbuf + 2 * TILE_BYTES,           t);
            load_tile8_async(A8l, NS, k0, nbuf + 2 * TILE_BYTES + TILE8,   t);
            load_tile8_async(B8h, NS, k0, nbuf + 2 * TILE_BYTES + 2*TILE8, t);
            load_tile8_async(B8l, NS, k0, nbuf + 2 * TILE_BYTES + 3*TILE8, t);
            asm volatile("cp.async.commit_group;" ::: "memory");
        }
    }

    // epilogue: split accumulators -> g_ohi/g_olo [p][c*32+e]
    int bg = bi * 4 + wm;
    #pragma unroll
    for (int i = 0; i < 2; i++) {
        int c_a = i * 16 + (lane >> 2);
        #pragma unroll
        for (int j = 0; j < 8; j++) {
            int n = wn * 64 + j * 8;
            int d = bj * 4 + (n >> 5);
            int e = (n & 31) + (lane & 3) * 2;
            size_t base = ((size_t)bg * NR + d) * KOUT;
            uint32_t h, l;
            split2(acc[i][j][0], acc[i][j][1], h, l);
            *(uint32_t*)(g_ohi + base + c_a * 32 + e) = h;
            *(uint32_t*)(g_olo + base + c_a * 32 + e) = l;
            split2(acc[i][j][2], acc[i][j][3], h, l);
            *(uint32_t*)(g_ohi + base + (c_a + 8) * 32 + e) = h;
            *(uint32_t*)(g_olo + base + (c_a + 8) * 32 + e) = l;
        }
    }
}

// ---------------------------------------------------------------------------
// Kernel 6: epilogue GEMM  out[p,f] = (sum_ce O[p,ce] wT[f,ce] + b[f]) * rnorm[p]
// ---------------------------------------------------------------------------
__global__ __launch_bounds__(256, 2) void gemm_epi_kernel(
    const float* __restrict__ outb, float* __restrict__ out)
{
    extern __shared__ __align__(16) unsigned char dsm[];
    uint32_t sb = smem_u32(dsm);

    int t = threadIdx.x, lane = t & 31, warp = t >> 5;
    int wm = warp >> 1, wn = warp & 1;
    size_t p0 = (size_t)blockIdx.x * 128;

    float acc[2][8][4];
    #pragma unroll
    for (int i = 0; i < 2; i++)
        #pragma unroll
        for (int j = 0; j < 8; j++)
            #pragma unroll
            for (int q = 0; q < 4; q++) acc[i][j][q] = 0.f;

    gemm_main(g_ohi + p0 * KOUT, g_olo + p0 * KOUT, KOUT,
              g_whi, g_wlo, KOUT,
              KOUT / 32, sb, acc);

    #pragma unroll
    for (int i = 0; i < 2; i++) {
        int m = wm * 32 + i * 16 + (lane >> 2);
        size_t pA = p0 + m, pB = p0 + m + 8;
        float rnA = g_rnorm[pA], rnB = g_rnorm[pB];
        #pragma unroll
        for (int j = 0; j < 8; j++) {
            int f = wn * 64 + j * 8 + (lane & 3) * 2;
            float b0 = __ldg(outb + f), b1 = __ldg(outb + f + 1);
            float2 vA = make_float2((acc[i][j][0] + b0) * rnA,
                                    (acc[i][j][1] + b1) * rnA);
            float2 vB = make_float2((acc[i][j][2] + b0) * rnB,
                                    (acc[i][j][3] + b1) * rnB);
            *(float2*)(out + pA * CZ + f) = vA;
            *(float2*)(out + pB * CZ + f) = vB;
        }
    }
}

// ---------------------------------------------------------------------------
extern "C" void kernel_launch(void* const* d_in, const int* in_sizes, int n_in,
                              void* d_out, int out_size)
{
    (void)in_sizes; (void)n_in; (void)out_size;
    const float* act     = (const float*)d_in[0];
    const float* mask    = (const float*)d_in[1];
    const float* ln_w    = (const float*)d_in[2];
    const float* ln_b    = (const float*)d_in[3];
    const float* left_w  = (const float*)d_in[4];
    const float* left_b  = (const float*)d_in[5];
    const float* right_w = (const float*)d_in[6];
    const float* right_b = (const float*)d_in[7];
    const float* out_w   = (const float*)d_in[8];
    const float* out_b   = (const float*)d_in[9];
    float* out = (float*)d_out;

    cudaFuncSetAttribute(gemm_outer_kernel,
                         cudaFuncAttributeMaxDynamicSharedMemorySize, OPIPE);
    cudaFuncSetAttribute(gemm_epi_kernel,
                         cudaFuncAttributeMaxDynamicSharedMemorySize, PIPE_BYTES);

    ln_proj_kernel<<<NS * NR, 256>>>(act, mask, ln_w, ln_b,
                                     left_w, left_b, right_w, right_b);
    transpose_split_kernel<<<dim3(MTOT / 32, NS / 32, 2), dim3(32, 8)>>>();
    norm_kernel<<<dim3(NR / 16, NR / 16), dim3(16, 16)>>>(mask);
    wprep_kernel<<<KOUT, CZ>>>(out_w);
    gemm_outer_kernel<<<dim3(96, 96), 256, OPIPE>>>();
    gemm_epi_kernel<<<NPAIR / 128, 256, PIPE_BYTES>>>(out_b, out);
}

// round 14
// speedup vs baseline: 1.2010x; 1.2010x over previous
#include <cuda_runtime.h>
#include <cuda_bf16.h>
#include <cuda_fp16.h>
#include <cstdint>

#define NS 512
#define NR 384
#define CM 256
#define CO 32
#define CZ 128
#define MTOT (NR*CO)        // 12288
#define NPAIR (NR*NR)       // 147456
#define KOUT 1024           // 32*32

// tiles: 32 elems x 2B (64B) + 16B pad
#define ROWB 80
#define TILE_BYTES (128 * ROWB)      // 10240
#define STAGE_BYTES (4 * TILE_BYTES) // 40960 (epi gemm: Ah,Al,Bh,Bl)
#define PIPE_BYTES (2 * STAGE_BYTES) // 81920
#define OSTAGE (2 * TILE_BYTES)      // 20480 (outer gemm: A,B fp16)
#define OPIPE (2 * OSTAGE)           // 40960

// ---------------- static device scratch ----------------
__device__ float g_leftf [NS * MTOT];            // [a][m] fp32 staging
__device__ float g_rightf[NS * MTOT];
__device__ float g_rnorm [NPAIR];
__device__ unsigned short g_l16[MTOT * NS];      // [m][a] fp16, K-major
__device__ unsigned short g_r16[MTOT * NS];
__device__ unsigned short g_ohi[(size_t)NPAIR * KOUT];  // outer [p][c*32+e] bf16 hi
__device__ unsigned short g_olo[(size_t)NPAIR * KOUT];  // outer bf16 lo
__device__ unsigned short g_whi[CZ * KOUT];      // w^T [f][ce] bf16 hi
__device__ unsigned short g_wlo[CZ * KOUT];

// ---------------- helpers ----------------
__device__ __forceinline__ uint32_t smem_u32(const void* p) {
    uint32_t a;
    asm("{ .reg .u64 t; cvta.to.shared.u64 t, %1; cvt.u32.u64 %0, t; }" : "=r"(a) : "l"(p));
    return a;
}
__device__ __forceinline__ void split_bf16(float x, unsigned short& h, unsigned short& l) {
    __nv_bfloat16 bh = __float2bfloat16(x);
    float r = x - __bfloat162float(bh);
    __nv_bfloat16 bl = __float2bfloat16(r);
    h = __bfloat16_as_ushort(bh);
    l = __bfloat16_as_ushort(bl);
}
__device__ __forceinline__ void split2(float x0, float x1, uint32_t& h, uint32_t& l) {
    unsigned short h0, l0, h1, l1;
    split_bf16(x0, h0, l0);
    split_bf16(x1, h1, l1);
    h = (uint32_t)h0 | ((uint32_t)h1 << 16);
    l = (uint32_t)l0 | ((uint32_t)l1 << 16);
}
__device__ __forceinline__ void ldsm_x4(uint32_t addr, uint32_t r[4]) {
    asm volatile("ldmatrix.sync.aligned.m8n8.x4.shared.b16 {%0,%1,%2,%3}, [%4];"
                 : "=r"(r[0]), "=r"(r[1]), "=r"(r[2]), "=r"(r[3]) : "r"(addr));
}
__device__ __forceinline__ void mma_bf16(float c[4], const uint32_t a[4],
                                         uint32_t b0, uint32_t b1) {
    asm volatile(
        "mma.sync.aligned.m16n8k16.row.col.f32.bf16.bf16.f32 "
        "{%0,%1,%2,%3}, {%4,%5,%6,%7}, {%8,%9}, {%0,%1,%2,%3};"
        : "+f"(c[0]), "+f"(c[1]), "+f"(c[2]), "+f"(c[3])
        : "r"(a[0]), "r"(a[1]), "r"(a[2]), "r"(a[3]), "r"(b0), "r"(b1));
}
__device__ __forceinline__ void mma_f16(float c[4], const uint32_t a[4],
                                        uint32_t b0, uint32_t b1) {
    asm volatile(
        "mma.sync.aligned.m16n8k16.row.col.f32.f16.f16.f32 "
        "{%0,%1,%2,%3}, {%4,%5,%6,%7}, {%8,%9}, {%0,%1,%2,%3};"
        : "+f"(c[0]), "+f"(c[1]), "+f"(c[2]), "+f"(c[3])
        : "r"(a[0]), "r"(a[1]), "r"(a[2]), "r"(a[3]), "r"(b0), "r"(b1));
}

// async-copy one [128 rows x 32 elem16] K-chunk tile into padded smem
__device__ __forceinline__ void load_tile_async(const unsigned short* __restrict__ g,
                                                size_t ldk, int k0,
                                                uint32_t sdst, int t) {
    #pragma unroll
    for (int i = 0; i < 2; i++) {
        int vid = i * 256 + t;      // 0..511
        int row = vid >> 2;         // 0..127
        int c8  = (vid & 3) << 3;   // 0,8,16,24
        const void* src = g + (size_t)row * ldk + k0 + c8;
        uint32_t dst = sdst + row * ROWB + c8 * 2;
        asm volatile("cp.async.cg.shared.global [%0], [%1], 16;"
                     :: "r"(dst), "l"(src) : "memory");
    }
}

// ---------------------------------------------------------------------------
// epi-gemm mainloop (bf16 split 3-pass, unchanged)
// ---------------------------------------------------------------------------
__device__ __forceinline__ void gemm_main(
    const unsigned short* __restrict__ Ah, const unsigned short* __restrict__ Al, size_t lda,
    const unsigned short* __restrict__ Bh, const unsigned short* __restrict__ Bl, size_t ldb,
    int nchunks, uint32_t sb, float acc[2][8][4])
{
    int t = threadIdx.x, lane = t & 31, warp = t >> 5;
    int mb = (warp >> 1) * 32, nb = (warp & 1) * 64;
    int g8 = lane >> 3;
    int a_row = (lane & 7) + ((g8 & 1) << 3);
    int a_k   = (g8 >> 1) << 3;
    int b_row = (lane & 7) + ((g8 >> 1) << 3);
    int b_k   = (g8 & 1) << 3;

    #pragma unroll
    for (int s = 0; s < 2; s++) {
        uint32_t bb = sb + s * STAGE_BYTES;
        int k0 = s * 32;
        load_tile_async(Ah, lda, k0, bb,                  t);
        load_tile_async(Al, lda, k0, bb + TILE_BYTES,     t);
        load_tile_async(Bh, ldb, k0, bb + 2 * TILE_BYTES, t);
        load_tile_async(Bl, ldb, k0, bb + 3 * TILE_BYTES, t);
        asm volatile("cp.async.commit_group;" ::: "memory");
    }

    for (int kc = 0; kc < nchunks; kc++) {
        if (kc + 1 < nchunks)
            asm volatile("cp.async.wait_group 1;" ::: "memory");
        else
            asm volatile("cp.async.wait_group 0;" ::: "memory");
        __syncthreads();

        uint32_t bb  = sb + (kc & 1) * STAGE_BYTES;
        uint32_t uAh = bb, uAl = bb + TILE_BYTES;
        uint32_t uBh = bb + 2 * TILE_BYTES, uBl = bb + 3 * TILE_BYTES;

        #pragma unroll
        for (int ks = 0; ks < 32; ks += 16) {
            uint32_t fAh[2][4], fAl[2][4];
            #pragma unroll
            for (int i = 0; i < 2; i++) {
                uint32_t ro = (uint32_t)((mb + i * 16 + a_row) * ROWB + (ks + a_k) * 2);
                ldsm_x4(uAh + ro, fAh[i]);
                ldsm_x4(uAl + ro, fAl[i]);
            }
            #pragma unroll
            for (int jj = 0; jj < 4; jj++) {
                uint32_t fBh[4], fBl[4];
                uint32_t ro = (uint32_t)((nb + jj * 16 + b_row) * ROWB + (ks + b_k) * 2);
                ldsm_x4(uBh + ro, fBh);
                ldsm_x4(uBl + ro, fBl);
                mma_bf16(acc[0][2 * jj],     fAh[0], fBh[0], fBh[1]);
                mma_bf16(acc[1][2 * jj],     fAh[1], fBh[0], fBh[1]);
                mma_bf16(acc[0][2 * jj + 1], fAh[0], fBh[2], fBh[3]);
                mma_bf16(acc[1][2 * jj + 1], fAh[1], fBh[2], fBh[3]);
                mma_bf16(acc[0][2 * jj],     fAh[0], fBl[0], fBl[1]);
                mma_bf16(acc[1][2 * jj],     fAh[1], fBl[0], fBl[1]);
                mma_bf16(acc[0][2 * jj + 1], fAh[0], fBl[2], fBl[3]);
                mma_bf16(acc[1][2 * jj + 1], fAh[1], fBl[2], fBl[3]);
                mma_bf16(acc[0][2 * jj],     fAl[0], fBh[0], fBh[1]);
                mma_bf16(acc[1][2 * jj],     fAl[1], fBh[0], fBh[1]);
                mma_bf16(acc[0][2 * jj + 1], fAl[0], fBh[2], fBh[3]);
                mma_bf16(acc[1][2 * jj + 1], fAl[1], fBh[2], fBh[3]);
            }
        }
        __syncthreads();

        if (kc + 2 < nchunks) {
            uint32_t nbuf = sb + (kc & 1) * STAGE_BYTES;
            int k0 = (kc + 2) * 32;
            load_tile_async(Ah, lda, k0, nbuf,                  t);
            load_tile_async(Al, lda, k0, nbuf + TILE_BYTES,     t);
            load_tile_async(Bh, ldb, k0, nbuf + 2 * TILE_BYTES, t);
            load_tile_async(Bl, ldb, k0, nbuf + 3 * TILE_BYTES, t);
            asm volatile("cp.async.commit_group;" ::: "memory");
        }
    }
}

// ---------------------------------------------------------------------------
// Kernel 1: LayerNorm + projections (fp32 staging, [a][m])
// ---------------------------------------------------------------------------
__global__ __launch_bounds__(256) void ln_proj_kernel(
    const float* __restrict__ act, const float* __restrict__ mask,
    const float* __restrict__ ln_w, const float* __restrict__ ln_b,
    const float* __restrict__ lw, const float* __restrict__ lb,
    const float* __restrict__ rw, const float* __restrict__ rb)
{
    int idx = blockIdx.x;
    int a = idx / NR, b = idx - a * NR;
    int t = threadIdx.x;
    __shared__ float s_act[CM];
    __shared__ float red1[8], red2[8];

    float x = act[(size_t)idx * CM + t];
    float s1 = x, s2 = x * x;
    #pragma unroll
    for (int o = 16; o; o >>= 1) {
        s1 += __shfl_xor_sync(0xffffffffu, s1, o);
        s2 += __shfl_xor_sync(0xffffffffu, s2, o);
    }
    int warp = t >> 5, lane = t & 31;
    if (lane == 0) { red1[warp] = s1; red2[warp] = s2; }
    __syncthreads();
    if (t < 32) {
        float a1 = (t < 8) ? red1[t] : 0.f;
        float a2 = (t < 8) ? red2[t] : 0.f;
        #pragma unroll
        for (int o = 4; o; o >>= 1) {
            a1 += __shfl_xor_sync(0xffffffffu, a1, o);
            a2 += __shfl_xor_sync(0xffffffffu, a2, o);
        }
        if (t == 0) { red1[0] = a1; red2[0] = a2; }
    }
    __syncthreads();
    float mu  = red1[0] * (1.f / CM);
    float var = red2[0] * (1.f / CM) - mu * mu;
    float inv = rsqrtf(var + 1e-5f);
    s_act[t] = (x - mu) * inv * ln_w[t] + ln_b[t];
    __syncthreads();

    int o = t >> 2, q = t & 3;
    const float* w = (o < CO) ? (lw + o * CM) : (rw + (o - CO) * CM);
    const float4* sa4 = (const float4*)(s_act + q * 64);
    const float4* w4  = (const float4*)(w + q * 64);
    float acc = 0.f;
    #pragma unroll
    for (int i = 0; i < 16; i++) {
        float4 xa = sa4[i], xw = w4[i];
        acc += xa.x * xw.x + xa.y * xw.y + xa.z * xw.z + xa.w * xw.w;
    }
    acc += __shfl_xor_sync(0xffffffffu, acc, 1);
    acc += __shfl_xor_sync(0xffffffffu, acc, 2);
    if (q == 0) {
        float mv = mask[a * NR + b];
        if (o < CO) g_leftf [(size_t)a * MTOT + b * CO + o]        = mv * (acc + lb[o]);
        else        g_rightf[(size_t)a * MTOT + b * CO + (o - CO)] = mv * (acc + rb[o - CO]);
    }
}

// ---------------------------------------------------------------------------
// Kernel 2: transpose [a][m] fp32 -> [m][a] fp16
// ---------------------------------------------------------------------------
__global__ __launch_bounds__(256) void transpose_split_kernel()
{
    __shared__ float tile[32][33];
    int m0 = blockIdx.x * 32, a0 = blockIdx.y * 32;
    const float* src = blockIdx.z ? g_rightf : g_leftf;
    unsigned short* d16 = blockIdx.z ? g_r16 : g_l16;
    int tx = threadIdx.x, ty = threadIdx.y;
    #pragma unroll
    for (int r = 0; r < 4; r++)
        tile[ty + 8 * r][tx] = src[(size_t)(a0 + ty + 8 * r) * MTOT + m0 + tx];
    __syncthreads();
    #pragma unroll
    for (int r = 0; r < 4; r++) {
        int m = m0 + ty + 8 * r;
        float x = tile[tx][ty + 8 * r];
        d16[(size_t)m * NS + a0 + tx] = __half_as_ushort(__float2half_rn(x));
    }
}

// ---------------------------------------------------------------------------
// Kernel 3: reciprocal mask norm
// ---------------------------------------------------------------------------
__global__ void norm_kernel(const float* __restrict__ mask)
{
    int b = blockIdx.x * 16 + threadIdx.x;
    int d = blockIdx.y * 16 + threadIdx.y;
    float acc = 0.f;
    #pragma unroll 8
    for (int a = 0; a < NS; a++)
        acc += mask[a * NR + b] * mask[a * NR + d];
    g_rnorm[b * NR + d] = 1.f / (1e-3f + acc);
}

// ---------------------------------------------------------------------------
// Kernel 4: w^T split prep  wT[f][c*32+e] = w[c,e,f]
// ---------------------------------------------------------------------------
__global__ void wprep_kernel(const float* __restrict__ w)
{
    int ce = blockIdx.x, f = threadIdx.x;
    unsigned short h, l;
    split_bf16(w[(size_t)ce * CZ + f], h, l);
    g_whi[(size_t)f * KOUT + ce] = h;
    g_wlo[(size_t)f * KOUT + ce] = l;
}

// ---------------------------------------------------------------------------
// Kernel 5: outer-product GEMM (12288x12288x512), single-pass fp16
// ---------------------------------------------------------------------------
__global__ __launch_bounds__(256, 2) void gemm_outer_kernel()
{
    extern __shared__ __align__(16) unsigned char dsm[];
    uint32_t sb = smem_u32(dsm);

    int bi = blockIdx.x, bj = blockIdx.y;
    int t = threadIdx.x, lane = t & 31, warp = t >> 5;
    int wm = warp >> 1, wn = warp & 1;
    int mb = wm * 32, nb = wn * 64;
    int g8 = lane >> 3;
    int a_row = (lane & 7) + ((g8 & 1) << 3);
    int a_k   = (g8 >> 1) << 3;
    int b_row = (lane & 7) + ((g8 >> 1) << 3);
    int b_k   = (g8 & 1) << 3;

    const unsigned short* A16 = g_l16 + (size_t)bi * 128 * NS;
    const unsigned short* B16 = g_r16 + (size_t)bj * 128 * NS;

    float acc[2][8][4];
    #pragma unroll
    for (int i = 0; i < 2; i++)
        #pragma unroll
        for (int j = 0; j < 8; j++)
            #pragma unroll
            for (int q = 0; q < 4; q++) acc[i][j][q] = 0.f;

    const int NCH = NS / 32;   // 16

    #pragma unroll
    for (int s = 0; s < 2; s++) {
        uint32_t bb = sb + s * OSTAGE;
        int k0 = s * 32;
        load_tile_async(A16, NS, k0, bb,              t);
        load_tile_async(B16, NS, k0, bb + TILE_BYTES, t);
        asm volatile("cp.async.commit_group;" ::: "memory");
    }

    for (int kc = 0; kc < NCH; kc++) {
        if (kc + 1 < NCH)
            asm volatile("cp.async.wait_group 1;" ::: "memory");
        else
            asm volatile("cp.async.wait_group 0;" ::: "memory");
        __syncthreads();

        uint32_t bb = sb + (kc & 1) * OSTAGE;
        uint32_t uA = bb, uB = bb + TILE_BYTES;

        #pragma unroll
        for (int ks = 0; ks < 32; ks += 16) {
            uint32_t fA[2][4];
            #pragma unroll
            for (int i = 0; i < 2; i++)
                ldsm_x4(uA + (uint32_t)((mb + i * 16 + a_row) * ROWB + (ks + a_k) * 2),
                        fA[i]);
            #pragma unroll
            for (int jj = 0; jj < 4; jj++) {
                uint32_t fB[4];
                ldsm_x4(uB + (uint32_t)((nb + jj * 16 + b_row) * ROWB + (ks + b_k) * 2),
                        fB);
                mma_f16(acc[0][2 * jj],     fA[0], fB[0], fB[1]);
                mma_f16(acc[1][2 * jj],     fA[1], fB[0], fB[1]);
                mma_f16(acc[0][2 * jj + 1], fA[0], fB[2], fB[3]);
                mma_f16(acc[1][2 * jj + 1], fA[1], fB[2], fB[3]);
            }
        }
        __syncthreads();

        if (kc + 2 < NCH) {
            uint32_t nbuf = sb + (kc & 1) * OSTAGE;
            int k0 = (kc + 2) * 32;
            load_tile_async(A16, NS, k0, nbuf,              t);
            load_tile_async(B16, NS, k0, nbuf + TILE_BYTES, t);
            asm volatile("cp.async.commit_group;" ::: "memory");
        }
    }

    // epilogue: split accumulators -> g_ohi/g_olo [p][c*32+e]
    int bg = bi * 4 + wm;
    #pragma unroll
    for (int i = 0; i < 2; i++) {
        int c_a = i * 16 + (lane >> 2);
        #pragma unroll
        for (int j = 0; j < 8; j++) {
            int n = wn * 64 + j * 8;
            int d = bj * 4 + (n >> 5);
            int e = (n & 31) + (lane & 3) * 2;
            size_t base = ((size_t)bg * NR + d) * KOUT;
            uint32_t h, l;
            split2(acc[i][j][0], acc[i][j][1], h, l);
            *(uint32_t*)(g_ohi + base + c_a * 32 + e) = h;
            *(uint32_t*)(g_olo + base + c_a * 32 + e) = l;
            split2(acc[i][j][2], acc[i][j][3], h, l);
            *(uint32_t*)(g_ohi + base + (c_a + 8) * 32 + e) = h;
            *(uint32_t*)(g_olo + base + (c_a + 8) * 32 + e) = l;
        }
    }
}

// ---------------------------------------------------------------------------
// Kernel 6: epilogue GEMM  out[p,f] = (sum_ce O[p,ce] wT[f,ce] + b[f]) * rnorm[p]
// ---------------------------------------------------------------------------
__global__ __launch_bounds__(256, 2) void gemm_epi_kernel(
    const float* __restrict__ outb, float* __restrict__ out)
{
    extern __shared__ __align__(16) unsigned char dsm[];
    uint32_t sb = smem_u32(dsm);

    int t = threadIdx.x, lane = t & 31, warp = t >> 5;
    int wm = warp >> 1, wn = warp & 1;
    size_t p0 = (size_t)blockIdx.x * 128;

    float acc[2][8][4];
    #pragma unroll
    for (int i = 0; i < 2; i++)
        #pragma unroll
        for (int j = 0; j < 8; j++)
            #pragma unroll
            for (int q = 0; q < 4; q++) acc[i][j][q] = 0.f;

    gemm_main(g_ohi + p0 * KOUT, g_olo + p0 * KOUT, KOUT,
              g_whi, g_wlo, KOUT,
              KOUT / 32, sb, acc);

    #pragma unroll
    for (int i = 0; i < 2; i++) {
        int m = wm * 32 + i * 16 + (lane >> 2);
        size_t pA = p0 + m, pB = p0 + m + 8;
        float rnA = g_rnorm[pA], rnB = g_rnorm[pB];
        #pragma unroll
        for (int j = 0; j < 8; j++) {
            int f = wn * 64 + j * 8 + (lane & 3) * 2;
            float b0 = __ldg(outb + f), b1 = __ldg(outb + f + 1);
            float2 vA = make_float2((acc[i][j][0] + b0) * rnA,
                                    (acc[i][j][1] + b1) * rnA);
            float2 vB = make_float2((acc[i][j][2] + b0) * rnB,
                                    (acc[i][j][3] + b1) * rnB);
            *(float2*)(out + pA * CZ + f) = vA;
            *(float2*)(out + pB * CZ + f) = vB;
        }
    }
}

// ---------------------------------------------------------------------------
extern "C" void kernel_launch(void* const* d_in, const int* in_sizes, int n_in,
                              void* d_out, int out_size)
{
    (void)in_sizes; (void)n_in; (void)out_size;
    const float* act     = (const float*)d_in[0];
    const float* mask    = (const float*)d_in[1];
    const float* ln_w    = (const float*)d_in[2];
    const float* ln_b    = (const float*)d_in[3];
    const float* left_w  = (const float*)d_in[4];
    const float* left_b  = (const float*)d_in[5];
    const float* right_w = (const float*)d_in[6];
    const float* right_b = (const float*)d_in[7];
    const float* out_w   = (const float*)d_in[8];
    const float* out_b   = (const float*)d_in[9];
    float* out = (float*)d_out;

    cudaFuncSetAttribute(gemm_outer_kernel,
                         cudaFuncAttributeMaxDynamicSharedMemorySize, OPIPE);
    cudaFuncSetAttribute(gemm_epi_kernel,
                         cudaFuncAttributeMaxDynamicSharedMemorySize, PIPE_BYTES);

    ln_proj_kernel<<<NS * NR, 256>>>(act, mask, ln_w, ln_b,
                                     left_w, left_b, right_w, right_b);
    transpose_split_kernel<<<dim3(MTOT / 32, NS / 32, 2), dim3(32, 8)>>>();
    norm_kernel<<<dim3(NR / 16, NR / 16), dim3(16, 16)>>>(mask);
    wprep_kernel<<<KOUT, CZ>>>(out_w);
    gemm_outer_kernel<<<dim3(96, 96), 256, OPIPE>>>();
    gemm_epi_kernel<<<NPAIR / 128, 256, PIPE_BYTES>>>(out_b, out);
}

// round 15
// speedup vs baseline: 1.2716x; 1.0588x over previous
#include <cuda_runtime.h>
#include <cuda_bf16.h>
#include <cuda_fp16.h>
#include <cstdint>

#define NS 512
#define NR 384
#define CM 256
#define CO 32
#define CZ 128
#define MTOT (NR*CO)        // 12288
#define NPAIR (NR*NR)       // 147456
#define KOUT 1024           // 32*32

// tiles: 32 elems x 2B (64B) + 16B pad
#define ROWB 80
#define TILE_BYTES (128 * ROWB)      // 10240
#define OSTAGE (2 * TILE_BYTES)      // 20480 (A,B fp16)
#define OPIPE (2 * OSTAGE)           // 40960

// ---------------- static device scratch ----------------
__device__ float g_leftf [NS * MTOT];            // [a][m] fp32 staging
__device__ float g_rightf[NS * MTOT];
__device__ float g_rnorm [NPAIR];
__device__ unsigned short g_l16[MTOT * NS];      // [m][a] fp16, K-major
__device__ unsigned short g_r16[MTOT * NS];
__device__ unsigned short g_o16[(size_t)NPAIR * KOUT];  // outer [p][c*32+e] fp16
__device__ unsigned short g_w16[CZ * KOUT];      // w^T [f][ce] fp16

// ---------------- helpers ----------------
__device__ __forceinline__ uint32_t smem_u32(const void* p) {
    uint32_t a;
    asm("{ .reg .u64 t; cvta.to.shared.u64 t, %1; cvt.u32.u64 %0, t; }" : "=r"(a) : "l"(p));
    return a;
}
__device__ __forceinline__ void ldsm_x4(uint32_t addr, uint32_t r[4]) {
    asm volatile("ldmatrix.sync.aligned.m8n8.x4.shared.b16 {%0,%1,%2,%3}, [%4];"
                 : "=r"(r[0]), "=r"(r[1]), "=r"(r[2]), "=r"(r[3]) : "r"(addr));
}
__device__ __forceinline__ void mma_f16(float c[4], const uint32_t a[4],
                                        uint32_t b0, uint32_t b1) {
    asm volatile(
        "mma.sync.aligned.m16n8k16.row.col.f32.f16.f16.f32 "
        "{%0,%1,%2,%3}, {%4,%5,%6,%7}, {%8,%9}, {%0,%1,%2,%3};"
        : "+f"(c[0]), "+f"(c[1]), "+f"(c[2]), "+f"(c[3])
        : "r"(a[0]), "r"(a[1]), "r"(a[2]), "r"(a[3]), "r"(b0), "r"(b1));
}
__device__ __forceinline__ uint32_t pack_f16x2(float a, float b) {
    __half2 h = __floats2half2_rn(a, b);
    return *(uint32_t*)&h;
}

// async-copy one [128 rows x 32 elem16] K-chunk tile into padded smem
__device__ __forceinline__ void load_tile_async(const unsigned short* __restrict__ g,
                                                size_t ldk, int k0,
                                                uint32_t sdst, int t) {
    #pragma unroll
    for (int i = 0; i < 2; i++) {
        int vid = i * 256 + t;      // 0..511
        int row = vid >> 2;         // 0..127
        int c8  = (vid & 3) << 3;   // 0,8,16,24
        const void* src = g + (size_t)row * ldk + k0 + c8;
        uint32_t dst = sdst + row * ROWB + c8 * 2;
        asm volatile("cp.async.cg.shared.global [%0], [%1], 16;"
                     :: "r"(dst), "l"(src) : "memory");
    }
}

// ---------------------------------------------------------------------------
// Shared single-pass fp16 mainloop: acc += A * B^T
// CTA tile 128x128, warps 4(M) x 2(N), warp tile 32x64, cp.async 2-stage.
// ---------------------------------------------------------------------------
__device__ __forceinline__ void gemm_main16(
    const unsigned short* __restrict__ A, size_t lda,
    const unsigned short* __restrict__ B, size_t ldb,
    int nchunks, uint32_t sb, float acc[2][8][4])
{
    int t = threadIdx.x, lane = t & 31, warp = t >> 5;
    int mb = (warp >> 1) * 32, nb = (warp & 1) * 64;
    int g8 = lane >> 3;
    int a_row = (lane & 7) + ((g8 & 1) << 3);
    int a_k   = (g8 >> 1) << 3;
    int b_row = (lane & 7) + ((g8 >> 1) << 3);
    int b_k   = (g8 & 1) << 3;

    #pragma unroll
    for (int s = 0; s < 2; s++) {
        uint32_t bb = sb + s * OSTAGE;
        int k0 = s * 32;
        load_tile_async(A, lda, k0, bb,              t);
        load_tile_async(B, ldb, k0, bb + TILE_BYTES, t);
        asm volatile("cp.async.commit_group;" ::: "memory");
    }

    for (int kc = 0; kc < nchunks; kc++) {
        if (kc + 1 < nchunks)
            asm volatile("cp.async.wait_group 1;" ::: "memory");
        else
            asm volatile("cp.async.wait_group 0;" ::: "memory");
        __syncthreads();

        uint32_t bb = sb + (kc & 1) * OSTAGE;
        uint32_t uA = bb, uB = bb + TILE_BYTES;

        #pragma unroll
        for (int ks = 0; ks < 32; ks += 16) {
            uint32_t fA[2][4];
            #pragma unroll
            for (int i = 0; i < 2; i++)
                ldsm_x4(uA + (uint32_t)((mb + i * 16 + a_row) * ROWB + (ks + a_k) * 2),
                        fA[i]);
            #pragma unroll
            for (int jj = 0; jj < 4; jj++) {
                uint32_t fB[4];
                ldsm_x4(uB + (uint32_t)((nb + jj * 16 + b_row) * ROWB + (ks + b_k) * 2),
                        fB);
                mma_f16(acc[0][2 * jj],     fA[0], fB[0], fB[1]);
                mma_f16(acc[1][2 * jj],     fA[1], fB[0], fB[1]);
                mma_f16(acc[0][2 * jj + 1], fA[0], fB[2], fB[3]);
                mma_f16(acc[1][2 * jj + 1], fA[1], fB[2], fB[3]);
            }
        }
        __syncthreads();

        if (kc + 2 < nchunks) {
            uint32_t nbuf = sb + (kc & 1) * OSTAGE;
            int k0 = (kc + 2) * 32;
            load_tile_async(A, lda, k0, nbuf,              t);
            load_tile_async(B, ldb, k0, nbuf + TILE_BYTES, t);
            asm volatile("cp.async.commit_group;" ::: "memory");
        }
    }
}

// ---------------------------------------------------------------------------
// Kernel 1: LayerNorm + projections (fp32 staging, [a][m])
// ---------------------------------------------------------------------------
__global__ __launch_bounds__(256) void ln_proj_kernel(
    const float* __restrict__ act, const float* __restrict__ mask,
    const float* __restrict__ ln_w, const float* __restrict__ ln_b,
    const float* __restrict__ lw, const float* __restrict__ lb,
    const float* __restrict__ rw, const float* __restrict__ rb)
{
    int idx = blockIdx.x;
    int a = idx / NR, b = idx - a * NR;
    int t = threadIdx.x;
    __shared__ float s_act[CM];
    __shared__ float red1[8], red2[8];

    float x = act[(size_t)idx * CM + t];
    float s1 = x, s2 = x * x;
    #pragma unroll
    for (int o = 16; o; o >>= 1) {
        s1 += __shfl_xor_sync(0xffffffffu, s1, o);
        s2 += __shfl_xor_sync(0xffffffffu, s2, o);
    }
    int warp = t >> 5, lane = t & 31;
    if (lane == 0) { red1[warp] = s1; red2[warp] = s2; }
    __syncthreads();
    if (t < 32) {
        float a1 = (t < 8) ? red1[t] : 0.f;
        float a2 = (t < 8) ? red2[t] : 0.f;
        #pragma unroll
        for (int o = 4; o; o >>= 1) {
            a1 += __shfl_xor_sync(0xffffffffu, a1, o);
            a2 += __shfl_xor_sync(0xffffffffu, a2, o);
        }
        if (t == 0) { red1[0] = a1; red2[0] = a2; }
    }
    __syncthreads();
    float mu  = red1[0] * (1.f / CM);
    float var = red2[0] * (1.f / CM) - mu * mu;
    float inv = rsqrtf(var + 1e-5f);
    s_act[t] = (x - mu) * inv * ln_w[t] + ln_b[t];
    __syncthreads();

    int o = t >> 2, q = t & 3;
    const float* w = (o < CO) ? (lw + o * CM) : (rw + (o - CO) * CM);
    const float4* sa4 = (const float4*)(s_act + q * 64);
    const float4* w4  = (const float4*)(w + q * 64);
    float acc = 0.f;
    #pragma unroll
    for (int i = 0; i < 16; i++) {
        float4 xa = sa4[i], xw = w4[i];
        acc += xa.x * xw.x + xa.y * xw.y + xa.z * xw.z + xa.w * xw.w;
    }
    acc += __shfl_xor_sync(0xffffffffu, acc, 1);
    acc += __shfl_xor_sync(0xffffffffu, acc, 2);
    if (q == 0) {
        float mv = mask[a * NR + b];
        if (o < CO) g_leftf [(size_t)a * MTOT + b * CO + o]        = mv * (acc + lb[o]);
        else        g_rightf[(size_t)a * MTOT + b * CO + (o - CO)] = mv * (acc + rb[o - CO]);
    }
}

// ---------------------------------------------------------------------------
// Kernel 2: transpose [a][m] fp32 -> [m][a] fp16
// ---------------------------------------------------------------------------
__global__ __launch_bounds__(256) void transpose_split_kernel()
{
    __shared__ float tile[32][33];
    int m0 = blockIdx.x * 32, a0 = blockIdx.y * 32;
    const float* src = blockIdx.z ? g_rightf : g_leftf;
    unsigned short* d16 = blockIdx.z ? g_r16 : g_l16;
    int tx = threadIdx.x, ty = threadIdx.y;
    #pragma unroll
    for (int r = 0; r < 4; r++)
        tile[ty + 8 * r][tx] = src[(size_t)(a0 + ty + 8 * r) * MTOT + m0 + tx];
    __syncthreads();
    #pragma unroll
    for (int r = 0; r < 4; r++) {
        int m = m0 + ty + 8 * r;
        float x = tile[tx][ty + 8 * r];
        d16[(size_t)m * NS + a0 + tx] = __half_as_ushort(__float2half_rn(x));
    }
}

// ---------------------------------------------------------------------------
// Kernel 3: reciprocal mask norm
// ---------------------------------------------------------------------------
__global__ void norm_kernel(const float* __restrict__ mask)
{
    int b = blockIdx.x * 16 + threadIdx.x;
    int d = blockIdx.y * 16 + threadIdx.y;
    float acc = 0.f;
    #pragma unroll 8
    for (int a = 0; a < NS; a++)
        acc += mask[a * NR + b] * mask[a * NR + d];
    g_rnorm[b * NR + d] = 1.f / (1e-3f + acc);
}

// ---------------------------------------------------------------------------
// Kernel 4: w^T prep  wT[f][c*32+e] = fp16(w[c,e,f])
// ---------------------------------------------------------------------------
__global__ void wprep_kernel(const float* __restrict__ w)
{
    int ce = blockIdx.x, f = threadIdx.x;
    g_w16[(size_t)f * KOUT + ce] =
        __half_as_ushort(__float2half_rn(w[(size_t)ce * CZ + f]));
}

// ---------------------------------------------------------------------------
// Kernel 5: outer-product GEMM (12288x12288x512), single-pass fp16
// ---------------------------------------------------------------------------
__global__ __launch_bounds__(256, 2) void gemm_outer_kernel()
{
    extern __shared__ __align__(16) unsigned char dsm[];
    uint32_t sb = smem_u32(dsm);

    int bi = blockIdx.x, bj = blockIdx.y;
    int t = threadIdx.x, lane = t & 31, warp = t >> 5;
    int wm = warp >> 1, wn = warp & 1;

    float acc[2][8][4];
    #pragma unroll
    for (int i = 0; i < 2; i++)
        #pragma unroll
        for (int j = 0; j < 8; j++)
            #pragma unroll
            for (int q = 0; q < 4; q++) acc[i][j][q] = 0.f;

    gemm_main16(g_l16 + (size_t)bi * 128 * NS, NS,
                g_r16 + (size_t)bj * 128 * NS, NS,
                NS / 32, sb, acc);

    // epilogue: pack fp16x2 -> g_o16 [p][c*32+e]
    int bg = bi * 4 + wm;
    #pragma unroll
    for (int i = 0; i < 2; i++) {
        int c_a = i * 16 + (lane >> 2);
        #pragma unroll
        for (int j = 0; j < 8; j++) {
            int n = wn * 64 + j * 8;
            int d = bj * 4 + (n >> 5);
            int e = (n & 31) + (lane & 3) * 2;
            size_t base = ((size_t)bg * NR + d) * KOUT;
            *(uint32_t*)(g_o16 + base + c_a * 32 + e) =
                pack_f16x2(acc[i][j][0], acc[i][j][1]);
            *(uint32_t*)(g_o16 + base + (c_a + 8) * 32 + e) =
                pack_f16x2(acc[i][j][2], acc[i][j][3]);
        }
    }
}

// ---------------------------------------------------------------------------
// Kernel 6: epilogue GEMM  out[p,f] = (sum_ce O[p,ce] wT[f,ce] + b[f]) * rnorm[p]
// ---------------------------------------------------------------------------
__global__ __launch_bounds__(256, 2) void gemm_epi_kernel(
    const float* __restrict__ outb, float* __restrict__ out)
{
    extern __shared__ __align__(16) unsigned char dsm[];
    uint32_t sb = smem_u32(dsm);

    int t = threadIdx.x, lane = t & 31, warp = t >> 5;
    int wm = warp >> 1, wn = warp & 1;
    size_t p0 = (size_t)blockIdx.x * 128;

    float acc[2][8][4];
    #pragma unroll
    for (int i = 0; i < 2; i++)
        #pragma unroll
        for (int j = 0; j < 8; j++)
            #pragma unroll
            for (int q = 0; q < 4; q++) acc[i][j][q] = 0.f;

    gemm_main16(g_o16 + p0 * KOUT, KOUT,
                g_w16, KOUT,
                KOUT / 32, sb, acc);

    #pragma unroll
    for (int i = 0; i < 2; i++) {
        int m = wm * 32 + i * 16 + (lane >> 2);
        size_t pA = p0 + m, pB = p0 + m + 8;
        float rnA = g_rnorm[pA], rnB = g_rnorm[pB];
        #pragma unroll
        for (int j = 0; j < 8; j++) {
            int f = wn * 64 + j * 8 + (lane & 3) * 2;
            float b0 = __ldg(outb + f), b1 = __ldg(outb + f + 1);
            float2 vA = make_float2((acc[i][j][0] + b0) * rnA,
                                    (acc[i][j][1] + b1) * rnA);
            float2 vB = make_float2((acc[i][j][2] + b0) * rnB,
                                    (acc[i][j][3] + b1) * rnB);
            *(float2*)(out + pA * CZ + f) = vA;
            *(float2*)(out + pB * CZ + f) = vB;
        }
    }
}

// ---------------------------------------------------------------------------
extern "C" void kernel_launch(void* const* d_in, const int* in_sizes, int n_in,
                              void* d_out, int out_size)
{
    (void)in_sizes; (void)n_in; (void)out_size;
    const float* act     = (const float*)d_in[0];
    const float* mask    = (const float*)d_in[1];
    const float* ln_w    = (const float*)d_in[2];
    const float* ln_b    = (const float*)d_in[3];
    const float* left_w  = (const float*)d_in[4];
    const float* left_b  = (const float*)d_in[5];
    const float* right_w = (const float*)d_in[6];
    const float* right_b = (const float*)d_in[7];
    const float* out_w   = (const float*)d_in[8];
    const float* out_b   = (const float*)d_in[9];
    float* out = (float*)d_out;

    cudaFuncSetAttribute(gemm_outer_kernel,
                         cudaFuncAttributeMaxDynamicSharedMemorySize, OPIPE);
    cudaFuncSetAttribute(gemm_epi_kernel,
                         cudaFuncAttributeMaxDynamicSharedMemorySize, OPIPE);

    ln_proj_kernel<<<NS * NR, 256>>>(act, mask, ln_w, ln_b,
                                     left_w, left_b, right_w, right_b);
    transpose_split_kernel<<<dim3(MTOT / 32, NS / 32, 2), dim3(32, 8)>>>();
    norm_kernel<<<dim3(NR / 16, NR / 16), dim3(16, 16)>>>(mask);
    wprep_kernel<<<KOUT, CZ>>>(out_w);
    gemm_outer_kernel<<<dim3(96, 96), 256, OPIPE>>>();
    gemm_epi_kernel<<<NPAIR / 128, 256, OPIPE>>>(out_b, out);
}

// round 16
// speedup vs baseline: 1.2863x; 1.0116x over previous
#include <cuda_runtime.h>
#include <cuda_bf16.h>
#include <cuda_fp16.h>
#include <cstdint>

#define NS 512
#define NR 384
#define CM 256
#define CO 32
#define CZ 128
#define MTOT (NR*CO)        // 12288
#define NPAIR (NR*NR)       // 147456
#define KOUT 1024           // 32*32

// tiles: 32 elems x 2B (64B) + 16B pad
#define ROWB 80
#define TILE_BYTES (128 * ROWB)      // 10240
#define OSTAGE (2 * TILE_BYTES)      // 20480 (A,B fp16)
#define NSTAGE 4
#define OPIPE (NSTAGE * OSTAGE)      // 81920

// ---------------- static device scratch ----------------
__device__ float g_leftf [NS * MTOT];            // [a][m] fp32 staging
__device__ float g_rightf[NS * MTOT];
__device__ float g_rnorm [NPAIR];
__device__ unsigned short g_l16[MTOT * NS];      // [m][a] fp16, K-major
__device__ unsigned short g_r16[MTOT * NS];
__device__ unsigned short g_o16[(size_t)NPAIR * KOUT];  // outer [p][c*32+e] fp16
__device__ unsigned short g_w16[CZ * KOUT];      // w^T [f][ce] fp16

// ---------------- helpers ----------------
__device__ __forceinline__ uint32_t smem_u32(const void* p) {
    uint32_t a;
    asm("{ .reg .u64 t; cvta.to.shared.u64 t, %1; cvt.u32.u64 %0, t; }" : "=r"(a) : "l"(p));
    return a;
}
__device__ __forceinline__ void ldsm_x4(uint32_t addr, uint32_t r[4]) {
    asm volatile("ldmatrix.sync.aligned.m8n8.x4.shared.b16 {%0,%1,%2,%3}, [%4];"
                 : "=r"(r[0]), "=r"(r[1]), "=r"(r[2]), "=r"(r[3]) : "r"(addr));
}
__device__ __forceinline__ void mma_f16(float c[4], const uint32_t a[4],
                                        uint32_t b0, uint32_t b1) {
    asm volatile(
        "mma.sync.aligned.m16n8k16.row.col.f32.f16.f16.f32 "
        "{%0,%1,%2,%3}, {%4,%5,%6,%7}, {%8,%9}, {%0,%1,%2,%3};"
        : "+f"(c[0]), "+f"(c[1]), "+f"(c[2]), "+f"(c[3])
        : "r"(a[0]), "r"(a[1]), "r"(a[2]), "r"(a[3]), "r"(b0), "r"(b1));
}
__device__ __forceinline__ uint32_t pack_f16x2(float a, float b) {
    __half2 h = __floats2half2_rn(a, b);
    return *(uint32_t*)&h;
}

// async-copy one [128 rows x 32 elem16] K-chunk tile into padded smem
__device__ __forceinline__ void load_tile_async(const unsigned short* __restrict__ g,
                                                size_t ldk, int k0,
                                                uint32_t sdst, int t) {
    #pragma unroll
    for (int i = 0; i < 2; i++) {
        int vid = i * 256 + t;      // 0..511
        int row = vid >> 2;         // 0..127
        int c8  = (vid & 3) << 3;   // 0,8,16,24
        const void* src = g + (size_t)row * ldk + k0 + c8;
        uint32_t dst = sdst + row * ROWB + c8 * 2;
        asm volatile("cp.async.cg.shared.global [%0], [%1], 16;"
                     :: "r"(dst), "l"(src) : "memory");
    }
}

// ---------------------------------------------------------------------------
// Single-pass fp16 mainloop, 4-stage multistage pipeline, 1 sync per chunk.
// CTA tile 128x128, warps 4(M) x 2(N), warp tile 32x64.
// ---------------------------------------------------------------------------
__device__ __forceinline__ void gemm_main16(
    const unsigned short* __restrict__ A, size_t lda,
    const unsigned short* __restrict__ B, size_t ldb,
    int nchunks, uint32_t sb, float acc[2][8][4])
{
    int t = threadIdx.x, lane = t & 31, warp = t >> 5;
    int mb = (warp >> 1) * 32, nb = (warp & 1) * 64;
    int g8 = lane >> 3;
    int a_row = (lane & 7) + ((g8 & 1) << 3);
    int a_k   = (g8 >> 1) << 3;
    int b_row = (lane & 7) + ((g8 >> 1) << 3);
    int b_k   = (g8 & 1) << 3;

    // prologue: stages 0..2
    #pragma unroll
    for (int s = 0; s < NSTAGE - 1; s++) {
        uint32_t bb = sb + s * OSTAGE;
        int k0 = s * 32;
        load_tile_async(A, lda, k0, bb,              t);
        load_tile_async(B, ldb, k0, bb + TILE_BYTES, t);
        asm volatile("cp.async.commit_group;" ::: "memory");
    }

    for (int kc = 0; kc < nchunks; kc++) {
        // stage kc must be complete: groups after it = min(2, nchunks-1-kc)
        int rem = nchunks - 1 - kc;
        if (rem >= 2)
            asm volatile("cp.async.wait_group 2;" ::: "memory");
        else if (rem == 1)
            asm volatile("cp.async.wait_group 1;" ::: "memory");
        else
            asm volatile("cp.async.wait_group 0;" ::: "memory");
        __syncthreads();

        // prefetch stage kc+3 into slot (kc+3)&3 == (kc-1)&3 (done being read)
        if (kc + NSTAGE - 1 < nchunks) {
            uint32_t nbuf = sb + ((kc + NSTAGE - 1) & (NSTAGE - 1)) * OSTAGE;
            int k0 = (kc + NSTAGE - 1) * 32;
            load_tile_async(A, lda, k0, nbuf,              t);
            load_tile_async(B, ldb, k0, nbuf + TILE_BYTES, t);
            asm volatile("cp.async.commit_group;" ::: "memory");
        }

        uint32_t bb = sb + (kc & (NSTAGE - 1)) * OSTAGE;
        uint32_t uA = bb, uB = bb + TILE_BYTES;

        #pragma unroll
        for (int ks = 0; ks < 32; ks += 16) {
            uint32_t fA[2][4];
            #pragma unroll
            for (int i = 0; i < 2; i++)
                ldsm_x4(uA + (uint32_t)((mb + i * 16 + a_row) * ROWB + (ks + a_k) * 2),
                        fA[i]);
            #pragma unroll
            for (int jj = 0; jj < 4; jj++) {
                uint32_t fB[4];
                ldsm_x4(uB + (uint32_t)((nb + jj * 16 + b_row) * ROWB + (ks + b_k) * 2),
                        fB);
                mma_f16(acc[0][2 * jj],     fA[0], fB[0], fB[1]);
                mma_f16(acc[1][2 * jj],     fA[1], fB[0], fB[1]);
                mma_f16(acc[0][2 * jj + 1], fA[0], fB[2], fB[3]);
                mma_f16(acc[1][2 * jj + 1], fA[1], fB[2], fB[3]);
            }
        }
    }
    __syncthreads();
}

// ---------------------------------------------------------------------------
// Kernel 1: LayerNorm + projections (fp32 staging, [a][m])
// ---------------------------------------------------------------------------
__global__ __launch_bounds__(256) void ln_proj_kernel(
    const float* __restrict__ act, const float* __restrict__ mask,
    const float* __restrict__ ln_w, const float* __restrict__ ln_b,
    const float* __restrict__ lw, const float* __restrict__ lb,
    const float* __restrict__ rw, const float* __restrict__ rb)
{
    int idx = blockIdx.x;
    int a = idx / NR, b = idx - a * NR;
    int t = threadIdx.x;
    __shared__ float s_act[CM];
    __shared__ float red1[8], red2[8];

    float x = act[(size_t)idx * CM + t];
    float s1 = x, s2 = x * x;
    #pragma unroll
    for (int o = 16; o; o >>= 1) {
        s1 += __shfl_xor_sync(0xffffffffu, s1, o);
        s2 += __shfl_xor_sync(0xffffffffu, s2, o);
    }
    int warp = t >> 5, lane = t & 31;
    if (lane == 0) { red1[warp] = s1; red2[warp] = s2; }
    __syncthreads();
    if (t < 32) {
        float a1 = (t < 8) ? red1[t] : 0.f;
        float a2 = (t < 8) ? red2[t] : 0.f;
        #pragma unroll
        for (int o = 4; o; o >>= 1) {
            a1 += __shfl_xor_sync(0xffffffffu, a1, o);
            a2 += __shfl_xor_sync(0xffffffffu, a2, o);
        }
        if (t == 0) { red1[0] = a1; red2[0] = a2; }
    }
    __syncthreads();
    float mu  = red1[0] * (1.f / CM);
    float var = red2[0] * (1.f / CM) - mu * mu;
    float inv = rsqrtf(var + 1e-5f);
    s_act[t] = (x - mu) * inv * ln_w[t] + ln_b[t];
    __syncthreads();

    int o = t >> 2, q = t & 3;
    const float* w = (o < CO) ? (lw + o * CM) : (rw + (o - CO) * CM);
    const float4* sa4 = (const float4*)(s_act + q * 64);
    const float4* w4  = (const float4*)(w + q * 64);
    float acc = 0.f;
    #pragma unroll
    for (int i = 0; i < 16; i++) {
        float4 xa = sa4[i], xw = w4[i];
        acc += xa.x * xw.x + xa.y * xw.y + xa.z * xw.z + xa.w * xw.w;
    }
    acc += __shfl_xor_sync(0xffffffffu, acc, 1);
    acc += __shfl_xor_sync(0xffffffffu, acc, 2);
    if (q == 0) {
        float mv = mask[a * NR + b];
        if (o < CO) g_leftf [(size_t)a * MTOT + b * CO + o]        = mv * (acc + lb[o]);
        else        g_rightf[(size_t)a * MTOT + b * CO + (o - CO)] = mv * (acc + rb[o - CO]);
    }
}

// ---------------------------------------------------------------------------
// Kernel 2: transpose [a][m] fp32 -> [m][a] fp16
// ---------------------------------------------------------------------------
__global__ __launch_bounds__(256) void transpose_split_kernel()
{
    __shared__ float tile[32][33];
    int m0 = blockIdx.x * 32, a0 = blockIdx.y * 32;
    const float* src = blockIdx.z ? g_rightf : g_leftf;
    unsigned short* d16 = blockIdx.z ? g_r16 : g_l16;
    int tx = threadIdx.x, ty = threadIdx.y;
    #pragma unroll
    for (int r = 0; r < 4; r++)
        tile[ty + 8 * r][tx] = src[(size_t)(a0 + ty + 8 * r) * MTOT + m0 + tx];
    __syncthreads();
    #pragma unroll
    for (int r = 0; r < 4; r++) {
        int m = m0 + ty + 8 * r;
        float x = tile[tx][ty + 8 * r];
        d16[(size_t)m * NS + a0 + tx] = __half_as_ushort(__float2half_rn(x));
    }
}

// ---------------------------------------------------------------------------
// Kernel 3: reciprocal mask norm
// ---------------------------------------------------------------------------
__global__ void norm_kernel(const float* __restrict__ mask)
{
    int b = blockIdx.x * 16 + threadIdx.x;
    int d = blockIdx.y * 16 + threadIdx.y;
    float acc = 0.f;
    #pragma unroll 8
    for (int a = 0; a < NS; a++)
        acc += mask[a * NR + b] * mask[a * NR + d];
    g_rnorm[b * NR + d] = 1.f / (1e-3f + acc);
}

// ---------------------------------------------------------------------------
// Kernel 4: w^T prep  wT[f][c*32+e] = fp16(w[c,e,f])
// ---------------------------------------------------------------------------
__global__ void wprep_kernel(const float* __restrict__ w)
{
    int ce = blockIdx.x, f = threadIdx.x;
    g_w16[(size_t)f * KOUT + ce] =
        __half_as_ushort(__float2half_rn(w[(size_t)ce * CZ + f]));
}

// ---------------------------------------------------------------------------
// Kernel 5: outer-product GEMM (12288x12288x512), single-pass fp16
// ---------------------------------------------------------------------------
__global__ __launch_bounds__(256, 2) void gemm_outer_kernel()
{
    extern __shared__ __align__(16) unsigned char dsm[];
    uint32_t sb = smem_u32(dsm);

    int bi = blockIdx.x, bj = blockIdx.y;
    int t = threadIdx.x, lane = t & 31, warp = t >> 5;
    int wm = warp >> 1, wn = warp & 1;

    float acc[2][8][4];
    #pragma unroll
    for (int i = 0; i < 2; i++)
        #pragma unroll
        for (int j = 0; j < 8; j++)
            #pragma unroll
            for (int q = 0; q < 4; q++) acc[i][j][q] = 0.f;

    gemm_main16(g_l16 + (size_t)bi * 128 * NS, NS,
                g_r16 + (size_t)bj * 128 * NS, NS,
                NS / 32, sb, acc);

    // epilogue: pack fp16x2 -> g_o16 [p][c*32+e]
    int bg = bi * 4 + wm;
    #pragma unroll
    for (int i = 0; i < 2; i++) {
        int c_a = i * 16 + (lane >> 2);
        #pragma unroll
        for (int j = 0; j < 8; j++) {
            int n = wn * 64 + j * 8;
            int d = bj * 4 + (n >> 5);
            int e = (n & 31) + (lane & 3) * 2;
            size_t base = ((size_t)bg * NR + d) * KOUT;
            *(uint32_t*)(g_o16 + base + c_a * 32 + e) =
                pack_f16x2(acc[i][j][0], acc[i][j][1]);
            *(uint32_t*)(g_o16 + base + (c_a + 8) * 32 + e) =
                pack_f16x2(acc[i][j][2], acc[i][j][3]);
        }
    }
}

// ---------------------------------------------------------------------------
// Kernel 6: epilogue GEMM  out[p,f] = (sum_ce O[p,ce] wT[f,ce] + b[f]) * rnorm[p]
// ---------------------------------------------------------------------------
__global__ __launch_bounds__(256, 2) void gemm_epi_kernel(
    const float* __restrict__ outb, float* __restrict__ out)
{
    extern __shared__ __align__(16) unsigned char dsm[];
    uint32_t sb = smem_u32(dsm);

    int t = threadIdx.x, lane = t & 31, warp = t >> 5;
    int wm = warp >> 1, wn = warp & 1;
    size_t p0 = (size_t)blockIdx.x * 128;

    float acc[2][8][4];
    #pragma unroll
    for (int i = 0; i < 2; i++)
        #pragma unroll
        for (int j = 0; j < 8; j++)
            #pragma unroll
            for (int q = 0; q < 4; q++) acc[i][j][q] = 0.f;

    gemm_main16(g_o16 + p0 * KOUT, KOUT,
                g_w16, KOUT,
                KOUT / 32, sb, acc);

    #pragma unroll
    for (int i = 0; i < 2; i++) {
        int m = wm * 32 + i * 16 + (lane >> 2);
        size_t pA = p0 + m, pB = p0 + m + 8;
        float rnA = g_rnorm[pA], rnB = g_rnorm[pB];
        #pragma unroll
        for (int j = 0; j < 8; j++) {
            int f = wn * 64 + j * 8 + (lane & 3) * 2;
            float b0 = __ldg(outb + f), b1 = __ldg(outb + f + 1);
            float2 vA = make_float2((acc[i][j][0] + b0) * rnA,
                                    (acc[i][j][1] + b1) * rnA);
            float2 vB = make_float2((acc[i][j][2] + b0) * rnB,
                                    (acc[i][j][3] + b1) * rnB);
            *(float2*)(out + pA * CZ + f) = vA;
            *(float2*)(out + pB * CZ + f) = vB;
        }
    }
}

// ---------------------------------------------------------------------------
extern "C" void kernel_launch(void* const* d_in, const int* in_sizes, int n_in,
                              void* d_out, int out_size)
{
    (void)in_sizes; (void)n_in; (void)out_size;
    const float* act     = (const float*)d_in[0];
    const float* mask    = (const float*)d_in[1];
    const float* ln_w    = (const float*)d_in[2];
    const float* ln_b    = (const float*)d_in[3];
    const float* left_w  = (const float*)d_in[4];
    const float* left_b  = (const float*)d_in[5];
    const float* right_w = (const float*)d_in[6];
    const float* right_b = (const float*)d_in[7];
    const float* out_w   = (const float*)d_in[8];
    const float* out_b   = (const float*)d_in[9];
    float* out = (float*)d_out;

    cudaFuncSetAttribute(gemm_outer_kernel,
                         cudaFuncAttributeMaxDynamicSharedMemorySize, OPIPE);
    cudaFuncSetAttribute(gemm_epi_kernel,
                         cudaFuncAttributeMaxDynamicSharedMemorySize, OPIPE);

    // NOTE launch order: gemm_outer moved to position 4 (where the ncu capture
    // window lands) so the next profile shows the dominant kernel. wprep is
    // independent of everything except gemm_epi.
    ln_proj_kernel<<<NS * NR, 256>>>(act, mask, ln_w, ln_b,
                                     left_w, left_b, right_w, right_b);
    transpose_split_kernel<<<dim3(MTOT / 32, NS / 32, 2), dim3(32, 8)>>>();
    norm_kernel<<<dim3(NR / 16, NR / 16), dim3(16, 16)>>>(mask);
    gemm_outer_kernel<<<dim3(96, 96), 256, OPIPE>>>();
    wprep_kernel<<<KOUT, CZ>>>(out_w);
    gemm_epi_kernel<<<NPAIR / 128, 256, OPIPE>>>(out_b, out);
}